// round 4
// baseline (speedup 1.0000x reference)
#include <cuda_runtime.h>
#include <math.h>

#define NMAX 100000
#define EMAX 3200000
#define SCAN_B 1024

// ---------------- device scratch (static, no allocs) ------------------------
__device__ int   g_is64;
__device__ int   g_src[EMAX];
__device__ int   g_dst[EMAX];
__device__ int   g_csr[EMAX];
__device__ int   g_deg[NMAX];          // 1 + in-degree (self loop included)
__device__ int   g_off[NMAX + 1];      // CSR offsets over real edges (deg-1)
__device__ int   g_cur[NMAX];          // scatter cursors
__device__ int   g_bsum[256];
__device__ int   g_bpre[256];
__device__ float g_dinv[NMAX];
__device__ __align__(16) float g_t1[NMAX * 16];  // (x@W1)*dinv
__device__ __align__(8)  float g_t2[NMAX * 2];   // (h@W2)*dinv

__device__ __forceinline__ void fma2(unsigned long long& d, unsigned long long a,
                                     unsigned long long b, unsigned long long c) {
    asm("fma.rn.f32x2 %0, %1, %2, %3;" : "=l"(d) : "l"(a), "l"(b), "l"(c));
}
__device__ __forceinline__ unsigned long long pack2(float lo, float hi) {
    unsigned long long r;
    asm("mov.b64 %0, {%1, %2};" : "=l"(r) : "f"(lo), "f"(hi));
    return r;
}
__device__ __forceinline__ void unpack2(float& lo, float& hi, unsigned long long v) {
    asm("mov.b64 {%0, %1}, %2;" : "=f"(lo), "=f"(hi) : "l"(v));
}

// ---------------------------------------------------------------------------
__global__ void k_detect(const int* __restrict__ ei32) {
    if (threadIdx.x == 0 && blockIdx.x == 0) {
        int all0 = 1;
        for (int i = 0; i < 64; i++)
            if (ei32[2 * i + 1] != 0) { all0 = 0; break; }
        g_is64 = all0;
    }
}

__global__ void k_deg_init(int N) {
    int i = blockIdx.x * blockDim.x + threadIdx.x;
    if (i < N) g_deg[i] = 1;
}

__global__ void k_convert(const void* __restrict__ ei, int E, int N) {
    int e = blockIdx.x * blockDim.x + threadIdx.x;
    if (e >= E) return;
    int s, d;
    if (g_is64) {
        const long long* p = (const long long*)ei;
        s = (int)p[e];
        d = (int)p[(long long)E + e];
    } else {
        const int* p = (const int*)ei;
        s = p[e];
        d = p[E + e];
    }
    if ((unsigned)s >= (unsigned)N) s = 0;
    if ((unsigned)d >= (unsigned)N) d = 0;
    g_src[e] = s;
    g_dst[e] = d;
    atomicAdd(&g_deg[d], 1);
}

// ---------------- CSR build: scan over (deg-1), then scatter ----------------
__global__ void k_scan_block(int N) {
    __shared__ int sh[SCAN_B];
    int tid = threadIdx.x;
    int i = blockIdx.x * SCAN_B + tid;
    int v = (i < N) ? (g_deg[i] - 1) : 0;
    sh[tid] = v;
    __syncthreads();
#pragma unroll
    for (int ofs = 1; ofs < SCAN_B; ofs <<= 1) {
        int add = (tid >= ofs) ? sh[tid - ofs] : 0;
        __syncthreads();
        sh[tid] += add;
        __syncthreads();
    }
    int incl = sh[tid];
    if (i < N) g_off[i] = incl - v;           // exclusive within block
    if (tid == SCAN_B - 1) g_bsum[blockIdx.x] = incl;
}

__global__ void k_scan_top(int nb) {
    __shared__ int sh[128];
    int tid = threadIdx.x;
    int v = (tid < nb) ? g_bsum[tid] : 0;
    sh[tid] = v;
    __syncthreads();
#pragma unroll
    for (int ofs = 1; ofs < 128; ofs <<= 1) {
        int add = (tid >= ofs) ? sh[tid - ofs] : 0;
        __syncthreads();
        sh[tid] += add;
        __syncthreads();
    }
    if (tid < nb) g_bpre[tid] = sh[tid] - v;  // exclusive
}

__global__ void k_scan_add(int N) {
    int i = blockIdx.x * blockDim.x + threadIdx.x;
    if (i >= N) return;
    int v = g_off[i] + g_bpre[i >> 10];
    g_off[i] = v;
    g_cur[i] = v;
    if (i == N - 1) g_off[N] = v + g_deg[i] - 1;
}

__global__ void k_scatter(int E) {
    int e = blockIdx.x * blockDim.x + threadIdx.x;
    if (e >= E) return;
    int d = g_dst[e];
    int pos = atomicAdd(&g_cur[d], 1);
    g_csr[pos] = g_src[e];
}

// ---------------- GEMM1: t1 = (x@W1)*dinv, smem-staged, f32x2 ---------------
// block = 128 threads, tile = 256 nodes (thread owns t and t+128),
// K processed in 4 phases of 32. xs rows padded to 33 words: conflict-free.
__global__ void __launch_bounds__(128) k_gemm1(const float* __restrict__ x,
                                               const float* __restrict__ W1, int N) {
    __shared__ float xs[256 * 33];
    __shared__ float wsm[2048];
    const unsigned long long* w64 = (const unsigned long long*)wsm;

    int t = threadIdx.x;
    int base = blockIdx.x * 256;

    for (int i = t; i < 2048; i += 128) wsm[i] = W1[i];

    unsigned long long acc0[8], acc1[8];
#pragma unroll
    for (int j = 0; j < 8; j++) { acc0[j] = 0ULL; acc1[j] = 0ULL; }

    for (int p = 0; p < 4; p++) {
        __syncthreads();
        // load 256 nodes x 32 k, coalesced, padded store
        for (int i = t; i < 256 * 32; i += 128) {
            int nl = i >> 5, f = i & 31;
            int node = base + nl;
            float v = (node < N) ? x[(size_t)node * 128 + p * 32 + f] : 0.0f;
            xs[nl * 33 + f] = v;
        }
        __syncthreads();
#pragma unroll 8
        for (int k = 0; k < 32; k++) {
            int kg = p * 32 + k;
            float x0 = xs[t * 33 + k];
            float x1 = xs[(t + 128) * 33 + k];
            unsigned long long xx0 = pack2(x0, x0);
            unsigned long long xx1 = pack2(x1, x1);
#pragma unroll
            for (int j2 = 0; j2 < 8; j2++) {
                unsigned long long wv = w64[kg * 8 + j2];
                fma2(acc0[j2], xx0, wv, acc0[j2]);
                fma2(acc1[j2], xx1, wv, acc1[j2]);
            }
        }
    }

    int n0 = base + t, n1 = base + t + 128;
    if (n0 < N) {
        float d = rsqrtf((float)g_deg[n0]);
        g_dinv[n0] = d;
        float* o = &g_t1[n0 * 16];
#pragma unroll
        for (int j2 = 0; j2 < 8; j2++) {
            float lo, hi; unpack2(lo, hi, acc0[j2]);
            o[2 * j2] = lo * d; o[2 * j2 + 1] = hi * d;
        }
    }
    if (n1 < N) {
        float d = rsqrtf((float)g_deg[n1]);
        g_dinv[n1] = d;
        float* o = &g_t1[n1 * 16];
#pragma unroll
        for (int j2 = 0; j2 < 8; j2++) {
            float lo, hi; unpack2(lo, hi, acc1[j2]);
            o[2 * j2] = lo * d; o[2 * j2 + 1] = hi * d;
        }
    }
}

// ---------------- layer-1 CSR gather + fused relu/bias/W2 -------------------
// 4 lanes per node (q = lane&3 handles 4 features). CSR read is same-address
// within the quad -> L1-merged. Epilogue reduces t2 partials via quad shuffle.
__global__ void k_edge1_csr(const float* __restrict__ b1,
                            const float* __restrict__ W2, int N) {
    __shared__ float w2s[32];
    __shared__ float b1s[16];
    if (threadIdx.x < 32) w2s[threadIdx.x] = W2[threadIdx.x];
    if (threadIdx.x < 16) b1s[threadIdx.x] = b1[threadIdx.x];
    __syncthreads();

    int t = blockIdx.x * blockDim.x + threadIdx.x;
    int node = t >> 2;
    if (node >= N) return;
    int q = t & 3;

    int beg = g_off[node];
    int end = g_off[node + 1];

    float4 acc = *(const float4*)&g_t1[node * 16 + q * 4];   // self-loop message
    for (int i = beg; i < end; i++) {
        int s = g_csr[i];
        float4 v = *(const float4*)&g_t1[s * 16 + q * 4];
        acc.x += v.x; acc.y += v.y; acc.z += v.z; acc.w += v.w;
    }

    float d = g_dinv[node];
    float h0 = fmaxf(fmaf(acc.x, d, b1s[q * 4 + 0]), 0.0f);
    float h1 = fmaxf(fmaf(acc.y, d, b1s[q * 4 + 1]), 0.0f);
    float h2 = fmaxf(fmaf(acc.z, d, b1s[q * 4 + 2]), 0.0f);
    float h3 = fmaxf(fmaf(acc.w, d, b1s[q * 4 + 3]), 0.0f);

    float p0 = h0 * w2s[(q * 4 + 0) * 2 + 0] + h1 * w2s[(q * 4 + 1) * 2 + 0]
             + h2 * w2s[(q * 4 + 2) * 2 + 0] + h3 * w2s[(q * 4 + 3) * 2 + 0];
    float p1 = h0 * w2s[(q * 4 + 0) * 2 + 1] + h1 * w2s[(q * 4 + 1) * 2 + 1]
             + h2 * w2s[(q * 4 + 2) * 2 + 1] + h3 * w2s[(q * 4 + 3) * 2 + 1];

    p0 += __shfl_xor_sync(0xffffffffu, p0, 1);
    p0 += __shfl_xor_sync(0xffffffffu, p0, 2);
    p1 += __shfl_xor_sync(0xffffffffu, p1, 1);
    p1 += __shfl_xor_sync(0xffffffffu, p1, 2);

    if (q == 0) {
        float2 o = make_float2(p0 * d, p1 * d);
        *(float2*)&g_t2[node * 2] = o;
    }
}

// ---------------- layer-2 CSR gather + fused log-softmax --------------------
__global__ void k_edge2_final(const float* __restrict__ b2,
                              float* __restrict__ out, int N) {
    int node = blockIdx.x * blockDim.x + threadIdx.x;
    if (node >= N) return;

    int beg = g_off[node];
    int end = g_off[node + 1];

    float2 acc = *(const float2*)&g_t2[node * 2];   // self loop
    for (int i = beg; i < end; i++) {
        int s = g_csr[i];
        float2 v = *(const float2*)&g_t2[s * 2];
        acc.x += v.x; acc.y += v.y;
    }

    float d = g_dinv[node];
    float v0 = fmaf(acc.x, d, __ldg(&b2[0]));
    float v1 = fmaf(acc.y, d, __ldg(&b2[1]));
    float m = fmaxf(v0, v1);
    float lse = m + logf(expf(v0 - m) + expf(v1 - m));
    float2 o = make_float2(v0 - lse, v1 - lse);
    *(float2*)&out[node * 2] = o;
}

// ---------------------------------------------------------------------------
extern "C" void kernel_launch(void* const* d_in, const int* in_sizes, int n_in,
                              void* d_out, int out_size) {
    const float* x  = (const float*)d_in[0];
    const void*  ei = d_in[1];
    const float* W1 = (const float*)d_in[2];
    const float* b1 = (const float*)d_in[3];
    const float* W2 = (const float*)d_in[4];
    const float* b2 = (const float*)d_in[5];
    float* out = (float*)d_out;

    int N = in_sizes[0] / 128;
    int E = in_sizes[1] / 2;

    const int T = 256;
    int nb = (N + SCAN_B - 1) / SCAN_B;

    k_detect<<<1, 32>>>((const int*)ei);
    k_deg_init<<<(N + T - 1) / T, T>>>(N);
    k_convert<<<(E + T - 1) / T, T>>>(ei, E, N);

    k_scan_block<<<nb, SCAN_B>>>(N);
    k_scan_top<<<1, 128>>>(nb);
    k_scan_add<<<(N + T - 1) / T, T>>>(N);
    k_scatter<<<(E + T - 1) / T, T>>>(E);

    k_gemm1<<<(N + 255) / 256, 128>>>(x, W1, N);

    k_edge1_csr<<<(N * 4 + T - 1) / T, T>>>(b1, W2, N);
    k_edge2_final<<<(N + T - 1) / T, T>>>(b2, out, N);
}

// round 5
// speedup vs baseline: 1.0371x; 1.0371x over previous
#include <cuda_runtime.h>
#include <math.h>

#define NMAX 100000
#define EMAX 3200000

// ---------------- device scratch (static, no allocs) ------------------------
__device__ int   g_is64;
__device__ __align__(8) int2 g_edge[EMAX];        // (src, dst)
__device__ int   g_deg[NMAX];                     // 1 + in-degree
__device__ float g_dinv[NMAX];
__device__ __align__(16) float g_t1[NMAX * 16];   // (x@W1)*dinv
__device__ __align__(16) float g_a1[NMAX * 16];   // layer-1 accumulator
__device__ __align__(8)  float g_t2[NMAX * 2];    // (h@W2)*dinv
__device__ __align__(8)  float g_a2[NMAX * 2];    // layer-2 accumulator

__device__ __forceinline__ void red_add_v4(float* p, float4 v) {
    asm volatile("red.global.add.v4.f32 [%0], {%1,%2,%3,%4};"
                 :: "l"(p), "f"(v.x), "f"(v.y), "f"(v.z), "f"(v.w) : "memory");
}
__device__ __forceinline__ void red_add_v2(float* p, float2 v) {
    asm volatile("red.global.add.v2.f32 [%0], {%1,%2};"
                 :: "l"(p), "f"(v.x), "f"(v.y) : "memory");
}
__device__ __forceinline__ void fma2(unsigned long long& d, unsigned long long a,
                                     unsigned long long b, unsigned long long c) {
    asm("fma.rn.f32x2 %0, %1, %2, %3;" : "=l"(d) : "l"(a), "l"(b), "l"(c));
}
__device__ __forceinline__ unsigned long long pack2(float lo, float hi) {
    unsigned long long r;
    asm("mov.b64 %0, {%1, %2};" : "=l"(r) : "f"(lo), "f"(hi));
    return r;
}
__device__ __forceinline__ void unpack2(float& lo, float& hi, unsigned long long v) {
    asm("mov.b64 {%0, %1}, %2;" : "=f"(lo), "=f"(hi) : "l"(v));
}

// ---------------------------------------------------------------------------
__global__ void k_detect(const int* __restrict__ ei32) {
    if (threadIdx.x == 0 && blockIdx.x == 0) {
        int all0 = 1;
        for (int i = 0; i < 64; i++)
            if (ei32[2 * i + 1] != 0) { all0 = 0; break; }
        g_is64 = all0;
    }
}

__global__ void k_deg_init(int N) {
    int i = blockIdx.x * blockDim.x + threadIdx.x;
    if (i < N) g_deg[i] = 1;
}

// convert edge indices -> int2, count degrees on dst
__global__ void k_convert(const void* __restrict__ ei, int E, int N) {
    int e = blockIdx.x * blockDim.x + threadIdx.x;
    if (e >= E) return;
    int s, d;
    if (g_is64) {
        const long long* p = (const long long*)ei;
        s = (int)p[e];
        d = (int)p[(long long)E + e];
    } else {
        const int* p = (const int*)ei;
        s = p[e];
        d = p[E + e];
    }
    if ((unsigned)s >= (unsigned)N) s = 0;
    if ((unsigned)d >= (unsigned)N) d = 0;
    g_edge[e] = make_int2(s, d);
    atomicAdd(&g_deg[d], 1);
}

// ---------------- GEMM1: t1 = (x@W1)*dinv, smem-staged, f32x2 ---------------
// block = 128 threads, tile = 256 nodes (thread owns t and t+128),
// K processed in 4 phases of 32. xs rows padded to 33 words: conflict-free.
// a1 initialized with self-loop message t1.
__global__ void __launch_bounds__(128) k_gemm1(const float* __restrict__ x,
                                               const float* __restrict__ W1, int N) {
    __shared__ float xs[256 * 33];
    __shared__ float wsm[2048];
    const unsigned long long* w64 = (const unsigned long long*)wsm;

    int t = threadIdx.x;
    int base = blockIdx.x * 256;

    for (int i = t; i < 2048; i += 128) wsm[i] = W1[i];

    unsigned long long acc0[8], acc1[8];
#pragma unroll
    for (int j = 0; j < 8; j++) { acc0[j] = 0ULL; acc1[j] = 0ULL; }

    for (int p = 0; p < 4; p++) {
        __syncthreads();
        for (int i = t; i < 256 * 32; i += 128) {
            int nl = i >> 5, f = i & 31;
            int node = base + nl;
            float v = (node < N) ? x[(size_t)node * 128 + p * 32 + f] : 0.0f;
            xs[nl * 33 + f] = v;
        }
        __syncthreads();
#pragma unroll 8
        for (int k = 0; k < 32; k++) {
            int kg = p * 32 + k;
            float x0 = xs[t * 33 + k];
            float x1 = xs[(t + 128) * 33 + k];
            unsigned long long xx0 = pack2(x0, x0);
            unsigned long long xx1 = pack2(x1, x1);
#pragma unroll
            for (int j2 = 0; j2 < 8; j2++) {
                unsigned long long wv = w64[kg * 8 + j2];
                fma2(acc0[j2], xx0, wv, acc0[j2]);
                fma2(acc1[j2], xx1, wv, acc1[j2]);
            }
        }
    }

    int n0 = base + t, n1 = base + t + 128;
    if (n0 < N) {
        float d = rsqrtf((float)g_deg[n0]);
        g_dinv[n0] = d;
        float4* o  = (float4*)&g_t1[n0 * 16];
        float4* a  = (float4*)&g_a1[n0 * 16];
#pragma unroll
        for (int q = 0; q < 4; q++) {
            float l0, h0, l1, h1;
            unpack2(l0, h0, acc0[q * 2]);
            unpack2(l1, h1, acc0[q * 2 + 1]);
            float4 v = make_float4(l0 * d, h0 * d, l1 * d, h1 * d);
            o[q] = v;
            a[q] = v;   // self-loop message
        }
    }
    if (n1 < N) {
        float d = rsqrtf((float)g_deg[n1]);
        g_dinv[n1] = d;
        float4* o  = (float4*)&g_t1[n1 * 16];
        float4* a  = (float4*)&g_a1[n1 * 16];
#pragma unroll
        for (int q = 0; q < 4; q++) {
            float l0, h0, l1, h1;
            unpack2(l0, h0, acc1[q * 2]);
            unpack2(l1, h1, acc1[q * 2 + 1]);
            float4 v = make_float4(l0 * d, h0 * d, l1 * d, h1 * d);
            o[q] = v;
            a[q] = v;   // self-loop message
        }
    }
}

// ---------------- layer-1 edge scatter: 4 lanes per edge --------------------
__global__ void k_edge1(int E) {
    int t = blockIdx.x * blockDim.x + threadIdx.x;
    int e = t >> 2;
    if (e >= E) return;
    int p = t & 3;
    int2 sd = g_edge[e];
    float4 v = *(const float4*)&g_t1[sd.x * 16 + p * 4];
    red_add_v4(&g_a1[sd.y * 16 + p * 4], v);
}

// ---------------- mid: h = relu(dinv*a1+b1); t2 = (h@W2)*dinv ----------------
__global__ void k_mid(const float* __restrict__ b1, const float* __restrict__ W2, int N) {
    __shared__ float w2[32];
    __shared__ float bb[16];
    if (threadIdx.x < 32) w2[threadIdx.x] = W2[threadIdx.x];
    if (threadIdx.x < 16) bb[threadIdx.x] = b1[threadIdx.x];
    __syncthreads();

    int node = blockIdx.x * blockDim.x + threadIdx.x;
    if (node >= N) return;

    float d = g_dinv[node];
    const float4* a1 = (const float4*)&g_a1[node * 16];
    float t0 = 0.0f, t1 = 0.0f;
#pragma unroll
    for (int q = 0; q < 4; q++) {
        float4 a = a1[q];
        float h0 = fmaxf(fmaf(a.x, d, bb[q * 4 + 0]), 0.0f);
        float h1 = fmaxf(fmaf(a.y, d, bb[q * 4 + 1]), 0.0f);
        float h2 = fmaxf(fmaf(a.z, d, bb[q * 4 + 2]), 0.0f);
        float h3 = fmaxf(fmaf(a.w, d, bb[q * 4 + 3]), 0.0f);
        t0 = fmaf(h0, w2[(q * 4 + 0) * 2 + 0], t0);
        t1 = fmaf(h0, w2[(q * 4 + 0) * 2 + 1], t1);
        t0 = fmaf(h1, w2[(q * 4 + 1) * 2 + 0], t0);
        t1 = fmaf(h1, w2[(q * 4 + 1) * 2 + 1], t1);
        t0 = fmaf(h2, w2[(q * 4 + 2) * 2 + 0], t0);
        t1 = fmaf(h2, w2[(q * 4 + 2) * 2 + 1], t1);
        t0 = fmaf(h3, w2[(q * 4 + 3) * 2 + 0], t0);
        t1 = fmaf(h3, w2[(q * 4 + 3) * 2 + 1], t1);
    }
    t0 *= d; t1 *= d;
    float2 t = make_float2(t0, t1);
    *(float2*)&g_t2[node * 2] = t;
    *(float2*)&g_a2[node * 2] = t;   // self-loop message
}

// ---------------- layer-2 edge scatter: 1 thread per edge -------------------
__global__ void k_edge2(int E) {
    int e = blockIdx.x * blockDim.x + threadIdx.x;
    if (e >= E) return;
    int2 sd = g_edge[e];
    float2 v = *(const float2*)&g_t2[sd.x * 2];
    red_add_v2(&g_a2[sd.y * 2], v);
}

// ---------------- final: out = log_softmax(dinv*a2 + b2) --------------------
__global__ void k_final(const float* __restrict__ b2, float* __restrict__ out, int N) {
    int node = blockIdx.x * blockDim.x + threadIdx.x;
    if (node >= N) return;
    float d = g_dinv[node];
    float2 a = *(const float2*)&g_a2[node * 2];
    float v0 = fmaf(a.x, d, __ldg(&b2[0]));
    float v1 = fmaf(a.y, d, __ldg(&b2[1]));
    float m = fmaxf(v0, v1);
    float lse = m + logf(expf(v0 - m) + expf(v1 - m));
    float2 o = make_float2(v0 - lse, v1 - lse);
    *(float2*)&out[node * 2] = o;
}

// ---------------------------------------------------------------------------
extern "C" void kernel_launch(void* const* d_in, const int* in_sizes, int n_in,
                              void* d_out, int out_size) {
    const float* x  = (const float*)d_in[0];
    const void*  ei = d_in[1];
    const float* W1 = (const float*)d_in[2];
    const float* b1 = (const float*)d_in[3];
    const float* W2 = (const float*)d_in[4];
    const float* b2 = (const float*)d_in[5];
    float* out = (float*)d_out;

    int N = in_sizes[0] / 128;
    int E = in_sizes[1] / 2;

    const int T = 256;
    k_detect<<<1, 32>>>((const int*)ei);
    k_deg_init<<<(N + T - 1) / T, T>>>(N);
    k_convert<<<(E + T - 1) / T, T>>>(ei, E, N);
    k_gemm1<<<(N + 255) / 256, 128>>>(x, W1, N);
    {
        long long total = (long long)E * 4;
        int blocks = (int)((total + T - 1) / T);
        k_edge1<<<blocks, T>>>(E);
    }
    k_mid<<<(N + T - 1) / T, T>>>(b1, W2, N);
    k_edge2<<<(E + T - 1) / T, T>>>(E);
    k_final<<<(N + T - 1) / T, T>>>(b2, out, N);
}

// round 6
// speedup vs baseline: 1.1974x; 1.1546x over previous
#include <cuda_runtime.h>
#include <math.h>

#define NMAX 100000
#define EMAX 3200000

// ---------------- device scratch (static, no allocs) ------------------------
__device__ int   g_is64;
__device__ __align__(8) int2 g_edge[EMAX];        // (src, dst)
__device__ int   g_deg[NMAX];                     // 1 + in-degree
__device__ float g_dinv[NMAX];
__device__ __align__(16) float g_t1[NMAX * 16];   // (x@W1)*dinv
__device__ __align__(16) float g_a1[NMAX * 16];   // layer-1 accumulator
__device__ __align__(8)  float g_t2[NMAX * 2];    // (h@W2)*dinv
__device__ __align__(8)  float g_a2[NMAX * 2];    // layer-2 accumulator

__device__ __forceinline__ void red_add_v4(float* p, float4 v) {
    asm volatile("red.global.add.v4.f32 [%0], {%1,%2,%3,%4};"
                 :: "l"(p), "f"(v.x), "f"(v.y), "f"(v.z), "f"(v.w) : "memory");
}
__device__ __forceinline__ void red_add_v2(float* p, float2 v) {
    asm volatile("red.global.add.v2.f32 [%0], {%1,%2};"
                 :: "l"(p), "f"(v.x), "f"(v.y) : "memory");
}
__device__ __forceinline__ void fma2(unsigned long long& d, unsigned long long a,
                                     unsigned long long b, unsigned long long c) {
    asm("fma.rn.f32x2 %0, %1, %2, %3;" : "=l"(d) : "l"(a), "l"(b), "l"(c));
}
__device__ __forceinline__ unsigned long long pack2(float lo, float hi) {
    unsigned long long r;
    asm("mov.b64 %0, {%1, %2};" : "=l"(r) : "f"(lo), "f"(hi));
    return r;
}
__device__ __forceinline__ void unpack2(float& lo, float& hi, unsigned long long v) {
    asm("mov.b64 {%0, %1}, %2;" : "=f"(lo), "=f"(hi) : "l"(v));
}

// ---------------------------------------------------------------------------
__global__ void k_detect(const int* __restrict__ ei32) {
    if (threadIdx.x == 0 && blockIdx.x == 0) {
        int all0 = 1;
        for (int i = 0; i < 64; i++)
            if (ei32[2 * i + 1] != 0) { all0 = 0; break; }
        g_is64 = all0;
    }
}

__global__ void k_deg_init(int N) {
    int i = blockIdx.x * blockDim.x + threadIdx.x;
    if (i < N) g_deg[i] = 1;
}

// convert edge indices -> int2, count degrees on dst
__global__ void k_convert(const void* __restrict__ ei, int E, int N) {
    int e = blockIdx.x * blockDim.x + threadIdx.x;
    if (e >= E) return;
    int s, d;
    if (g_is64) {
        const long long* p = (const long long*)ei;
        s = (int)p[e];
        d = (int)p[(long long)E + e];
    } else {
        const int* p = (const int*)ei;
        s = p[e];
        d = p[E + e];
    }
    if ((unsigned)s >= (unsigned)N) s = 0;
    if ((unsigned)d >= (unsigned)N) d = 0;
    g_edge[e] = make_int2(s, d);
    atomicAdd(&g_deg[d], 1);
}

// ---------------- GEMM1: t1 = (x@W1)*dinv, smem-staged, f32x2 ---------------
// 256 threads/block, 1 node/thread, K in 8 phases of 16 floats.
// xs rows padded to 17 words (conflict-free); smem = 17.4KB + 8KB W = 25.4KB.
__global__ void __launch_bounds__(256) k_gemm1(const float* __restrict__ x,
                                               const float* __restrict__ W1, int N) {
    __shared__ float xs[256 * 17];
    __shared__ float wsm[2048];
    const unsigned long long* w64 = (const unsigned long long*)wsm;

    int t = threadIdx.x;
    int base = blockIdx.x * 256;
    int node = base + t;

    for (int i = t; i < 2048; i += 256) wsm[i] = W1[i];

    unsigned long long acc[8];
#pragma unroll
    for (int j = 0; j < 8; j++) acc[j] = 0ULL;

#pragma unroll 1
    for (int p = 0; p < 8; p++) {
        __syncthreads();
#pragma unroll
        for (int i = t; i < 256 * 16; i += 256) {
            int nl = i >> 4, f = i & 15;
            int nn = base + nl;
            float v = (nn < N) ? x[(size_t)nn * 128 + p * 16 + f] : 0.0f;
            xs[nl * 17 + f] = v;
        }
        __syncthreads();
#pragma unroll
        for (int k = 0; k < 16; k++) {
            int kg = p * 16 + k;
            float xk = xs[t * 17 + k];
            unsigned long long xx = pack2(xk, xk);
#pragma unroll
            for (int j2 = 0; j2 < 8; j2++) {
                fma2(acc[j2], xx, w64[kg * 8 + j2], acc[j2]);
            }
        }
    }

    if (node < N) {
        float d = rsqrtf((float)g_deg[node]);
        g_dinv[node] = d;
        float4* o = (float4*)&g_t1[node * 16];
        float4* a = (float4*)&g_a1[node * 16];
#pragma unroll
        for (int q = 0; q < 4; q++) {
            float l0, h0, l1, h1;
            unpack2(l0, h0, acc[q * 2]);
            unpack2(l1, h1, acc[q * 2 + 1]);
            float4 v = make_float4(l0 * d, h0 * d, l1 * d, h1 * d);
            o[q] = v;
            a[q] = v;   // self-loop message
        }
    }
}

// ---------------- layer-1 edge scatter: 4 lanes per edge --------------------
__global__ void k_edge1(int E) {
    int t = blockIdx.x * blockDim.x + threadIdx.x;
    int e = t >> 2;
    if (e >= E) return;
    int p = t & 3;
    int2 sd = g_edge[e];
    float4 v = *(const float4*)&g_t1[sd.x * 16 + p * 4];
    red_add_v4(&g_a1[sd.y * 16 + p * 4], v);
}

// ---------------- mid: h = relu(dinv*a1+b1); t2 = (h@W2)*dinv ----------------
__global__ void k_mid(const float* __restrict__ b1, const float* __restrict__ W2, int N) {
    __shared__ float w2[32];
    __shared__ float bb[16];
    if (threadIdx.x < 32) w2[threadIdx.x] = W2[threadIdx.x];
    if (threadIdx.x < 16) bb[threadIdx.x] = b1[threadIdx.x];
    __syncthreads();

    int node = blockIdx.x * blockDim.x + threadIdx.x;
    if (node >= N) return;

    float d = g_dinv[node];
    const float4* a1 = (const float4*)&g_a1[node * 16];
    float t0 = 0.0f, t1 = 0.0f;
#pragma unroll
    for (int q = 0; q < 4; q++) {
        float4 a = a1[q];
        float h0 = fmaxf(fmaf(a.x, d, bb[q * 4 + 0]), 0.0f);
        float h1 = fmaxf(fmaf(a.y, d, bb[q * 4 + 1]), 0.0f);
        float h2 = fmaxf(fmaf(a.z, d, bb[q * 4 + 2]), 0.0f);
        float h3 = fmaxf(fmaf(a.w, d, bb[q * 4 + 3]), 0.0f);
        t0 = fmaf(h0, w2[(q * 4 + 0) * 2 + 0], t0);
        t1 = fmaf(h0, w2[(q * 4 + 0) * 2 + 1], t1);
        t0 = fmaf(h1, w2[(q * 4 + 1) * 2 + 0], t0);
        t1 = fmaf(h1, w2[(q * 4 + 1) * 2 + 1], t1);
        t0 = fmaf(h2, w2[(q * 4 + 2) * 2 + 0], t0);
        t1 = fmaf(h2, w2[(q * 4 + 2) * 2 + 1], t1);
        t0 = fmaf(h3, w2[(q * 4 + 3) * 2 + 0], t0);
        t1 = fmaf(h3, w2[(q * 4 + 3) * 2 + 1], t1);
    }
    t0 *= d; t1 *= d;
    float2 t = make_float2(t0, t1);
    *(float2*)&g_t2[node * 2] = t;
    *(float2*)&g_a2[node * 2] = t;   // self-loop message
}

// ---------------- layer-2 edge scatter: 1 thread per edge -------------------
__global__ void k_edge2(int E) {
    int e = blockIdx.x * blockDim.x + threadIdx.x;
    if (e >= E) return;
    int2 sd = g_edge[e];
    float2 v = *(const float2*)&g_t2[sd.x * 2];
    red_add_v2(&g_a2[sd.y * 2], v);
}

// ---------------- final: out = log_softmax(dinv*a2 + b2) --------------------
__global__ void k_final(const float* __restrict__ b2, float* __restrict__ out, int N) {
    int node = blockIdx.x * blockDim.x + threadIdx.x;
    if (node >= N) return;
    float d = g_dinv[node];
    float2 a = *(const float2*)&g_a2[node * 2];
    float v0 = fmaf(a.x, d, __ldg(&b2[0]));
    float v1 = fmaf(a.y, d, __ldg(&b2[1]));
    float m = fmaxf(v0, v1);
    float lse = m + logf(expf(v0 - m) + expf(v1 - m));
    float2 o = make_float2(v0 - lse, v1 - lse);
    *(float2*)&out[node * 2] = o;
}

// ---------------------------------------------------------------------------
extern "C" void kernel_launch(void* const* d_in, const int* in_sizes, int n_in,
                              void* d_out, int out_size) {
    const float* x  = (const float*)d_in[0];
    const void*  ei = d_in[1];
    const float* W1 = (const float*)d_in[2];
    const float* b1 = (const float*)d_in[3];
    const float* W2 = (const float*)d_in[4];
    const float* b2 = (const float*)d_in[5];
    float* out = (float*)d_out;

    int N = in_sizes[0] / 128;
    int E = in_sizes[1] / 2;

    const int T = 256;
    k_detect<<<1, 32>>>((const int*)ei);
    k_deg_init<<<(N + T - 1) / T, T>>>(N);
    k_convert<<<(E + T - 1) / T, T>>>(ei, E, N);
    k_gemm1<<<(N + 255) / 256, 256>>>(x, W1, N);
    {
        long long total = (long long)E * 4;
        int blocks = (int)((total + T - 1) / T);
        k_edge1<<<blocks, T>>>(E);
    }
    k_mid<<<(N + T - 1) / T, T>>>(b1, W2, N);
    k_edge2<<<(E + T - 1) / T, T>>>(E);
    k_final<<<(N + T - 1) / T, T>>>(b2, out, N);
}